// round 12
// baseline (speedup 1.0000x reference)
#include <cuda_runtime.h>
#include <cuda_fp16.h>

// ---------------- problem / tiling constants ----------------
#define NN      256
#define NTILES  2048          // 262144 / 128 M-rows per tile
#define GRID    152           // persistent, 1 CTA / SM on GB300
#define NPAIR   (GRID / 2)    // CTA pairs walking the same M-tiles
#define THREADS 256

// ---------------- smem layout (bytes) ----------------
// A buffer: one chunk [128 rows x 64 k] fp16, 128B rows, SW128 swizzle
#define A_BUF    0
#define A_BYTES  16384
// B resident: wh then wl, each 4 chunks of [128 n-rows x 64 k] fp16 SW128
#define B_BASE   16384
#define B_CHUNK  16384
#define BL_OFF   (4 * B_CHUNK)              // 65536
#define SMEM_TOTAL (B_BASE + 8 * B_CHUNK)   // 147456

// ---------------- device globals (scratch; no runtime alloc) ----------------
__device__ float g_scale;
__device__ __align__(16) float  g_M [NN * NN];
__device__ __align__(16) float  g_M2[NN * NN];
__device__ __align__(16) float  g_M4[NN * NN];
__device__ __align__(16) __half g_WH[NN * NN];
__device__ __align__(16) __half g_WL[NN * NN];

// ---------------- helpers ----------------
__device__ __forceinline__ unsigned smem_u32(const void* p) {
    unsigned a;
    asm("{ .reg .u64 t; cvta.to.shared.u64 t, %1; cvt.u32.u64 %0, t; }" : "=r"(a) : "l"(p));
    return a;
}
__device__ __forceinline__ void ldsm_x4(unsigned& r0, unsigned& r1, unsigned& r2, unsigned& r3,
                                        unsigned addr) {
    asm volatile("ldmatrix.sync.aligned.m8n8.x4.shared.b16 {%0,%1,%2,%3}, [%4];"
                 : "=r"(r0), "=r"(r1), "=r"(r2), "=r"(r3) : "r"(addr));
}
__device__ __forceinline__ void mma16816(float* d, const unsigned* a, const unsigned* b) {
    asm volatile("mma.sync.aligned.m16n8k16.row.col.f32.f16.f16.f32 "
                 "{%0,%1,%2,%3}, {%4,%5,%6,%7}, {%8,%9}, {%0,%1,%2,%3};"
                 : "+f"(d[0]), "+f"(d[1]), "+f"(d[2]), "+f"(d[3])
                 : "r"(a[0]), "r"(a[1]), "r"(a[2]), "r"(a[3]), "r"(b[0]), "r"(b[1]));
}
__device__ __forceinline__ unsigned h2u(__half2 h) { return *reinterpret_cast<unsigned*>(&h); }

// ========================= prep: C = A^T A (256x256) =========================
// grid 128, block 256; CTA b computes output rows 2b, 2b+1.
__global__ void ata_kernel(const float* __restrict__ W, int mode) {
    const float* A = (mode == 0) ? W : (mode == 1 ? g_M : g_M2);
    float* C = (mode == 0) ? g_M : (mode == 1 ? g_M2 : g_M4);
    __shared__ float2 cols[NN];
    int b = blockIdx.x, t = threadIdx.x;
    cols[t] = make_float2(A[t * NN + 2 * b], A[t * NN + 2 * b + 1]);
    __syncthreads();
    float a0 = 0.f, a1 = 0.f;
#pragma unroll 8
    for (int k = 0; k < NN; k++) {
        float a = A[k * NN + t];
        float2 cv = cols[k];
        a0 += cv.x * a;
        a1 += cv.y * a;
    }
    C[(2 * b) * NN + t] = a0;
    C[(2 * b + 1) * NN + t] = a1;
}

// ========================= prep: power iteration on M4 =========================
__device__ __forceinline__ float blk_sum(float val) {
    __shared__ float red[8];
    int lane = threadIdx.x & 31, w = threadIdx.x >> 5;
#pragma unroll
    for (int o = 16; o; o >>= 1) val += __shfl_xor_sync(0xffffffffu, val, o);
    if (lane == 0) red[w] = val;
    __syncthreads();
    float r = red[0] + red[1] + red[2] + red[3] + red[4] + red[5] + red[6] + red[7];
    __syncthreads();
    return r;
}

__global__ void pi_kernel(const float* __restrict__ W) {
    __shared__ float vv[NN];
    int t = threadIdx.x;
    vv[t] = 0.0625f; // 1/sqrt(256)
    __syncthreads();
    const float4* mr = reinterpret_cast<const float4*>(g_M4 + t * NN);
    for (int it = 0; it < 5; it++) {       // (M^4)^5 == (W^T W)^20
        float s = 0.f;
#pragma unroll 8
        for (int j = 0; j < 64; j++) {
            float4 m = mr[j];
            s += m.x * vv[4 * j] + m.y * vv[4 * j + 1] + m.z * vv[4 * j + 2] + m.w * vv[4 * j + 3];
        }
        float ss = blk_sum(s * s);
        vv[t] = s * (1.f / (sqrtf(ss) + 1e-12f));
        __syncthreads();
    }
    // sigma = ||W v|| + 1e-12 ; scale = 1/sigma
    const float4* wr = reinterpret_cast<const float4*>(W + t * NN);
    float s = 0.f;
#pragma unroll 8
    for (int j = 0; j < 64; j++) {
        float4 w4 = wr[j];
        s += w4.x * vv[4 * j] + w4.y * vv[4 * j + 1] + w4.z * vv[4 * j + 2] + w4.w * vv[4 * j + 3];
    }
    float ss = blk_sum(s * s);
    if (t == 0) g_scale = 1.f / (sqrtf(ss) + 1e-12f);
}

// ================= prep: W_eff -> fp16 hi/lo, zero diag =================
__global__ void convert_kernel(const float* __restrict__ W) {
    float sc = g_scale;
    int base = blockIdx.x * 512 + threadIdx.x;
#pragma unroll
    for (int r = 0; r < 2; r++) {
        int idx = base + r * 256;
        int i = idx >> 8, j = idx & 255;
        float w = (i == j) ? 0.f : W[idx] * sc;
        __half h = __float2half_rn(w);
        g_WH[idx] = h;
        g_WL[idx] = __float2half_rn(w - __half2float(h));
    }
}

// ========================= main GEMM: out = x16 @ (Wh+Wl)^T =========================
__global__ void __launch_bounds__(THREADS, 1)
gemm_kernel(const float* __restrict__ x, float* __restrict__ out) {
    extern __shared__ char sm[];
    unsigned sbase = smem_u32(sm);
    const int tid = threadIdx.x, wid = tid >> 5, lane = tid & 31;
    const int h0 = (blockIdx.x & 1) * 128;     // this CTA's N-half
    const int pair = blockIdx.x >> 1;
    const int wm = (wid & 3) * 32;             // warp M offset in tile
    const int wn = (wid >> 2) * 64;            // warp N offset in half

    // ---- resident B: wh/wl rows [h0, h0+128), chunked SW128 ----
    {
        const uint4* WH = reinterpret_cast<const uint4*>(g_WH);
        const uint4* WL = reinterpret_cast<const uint4*>(g_WL);
        for (int v = tid; v < 4096; v += THREADS) {
            int n = v >> 5, kb8 = v & 31;      // 32 x 16B units per 512B row
            int chunk = kb8 >> 3, kb = kb8 & 7;
            unsigned off = chunk * B_CHUNK + n * 128 + ((kb * 16) ^ ((n & 7) << 4));
            *reinterpret_cast<uint4*>(sm + B_BASE + off) = WH[(h0 + n) * 32 + kb8];
            *reinterpret_cast<uint4*>(sm + B_BASE + BL_OFF + off) = WL[(h0 + n) * 32 + kb8];
        }
    }
    __syncthreads();

    // per-thread ldmatrix address components
    const unsigned arow = wm + (lane & 15);
    const unsigned akb = ((lane >> 4) & 1) * 16;       // bytes
    const unsigned brow = wn + ((lane >> 4) & 1) * 8 + (lane & 7);
    const unsigned bkb = ((lane >> 3) & 1) * 16;       // bytes
    const unsigned phase = (lane & 7) << 4;

    // ---- prefetch chunk (t=pair, c=0) ----
    float4 pre[8];
    {
        const float4* xt = reinterpret_cast<const float4*>(x + (size_t)pair * (128 * NN));
#pragma unroll
        for (int i = 0; i < 4; i++) {
            int v = i * 256 + tid;
            int row = v >> 3, kb = v & 7;
            const float4* p = xt + row * 64 + kb * 2;
            pre[2 * i] = p[0];
            pre[2 * i + 1] = p[1];
        }
    }

    for (int t = pair; t < NTILES; t += NPAIR) {
        float acc[2][8][4];
#pragma unroll
        for (int mt = 0; mt < 2; mt++)
#pragma unroll
            for (int nt = 0; nt < 8; nt++)
#pragma unroll
                for (int q = 0; q < 4; q++) acc[mt][nt][q] = 0.f;

        for (int c = 0; c < 4; c++) {
            // ---- convert fp32 -> fp16, STS swizzled ----
#pragma unroll
            for (int i = 0; i < 4; i++) {
                int v = i * 256 + tid;
                int row = v >> 3, kb = v & 7;
                float4 a = pre[2 * i], b = pre[2 * i + 1];
                __half2 H0 = __float22half2_rn(make_float2(a.x, a.y));
                __half2 H1 = __float22half2_rn(make_float2(a.z, a.w));
                __half2 H2 = __float22half2_rn(make_float2(b.x, b.y));
                __half2 H3 = __float22half2_rn(make_float2(b.z, b.w));
                unsigned off = (unsigned)(row * 128) + (((unsigned)(kb * 16)) ^ ((row & 7) << 4));
                *reinterpret_cast<uint4*>(sm + A_BUF + off) =
                    make_uint4(h2u(H0), h2u(H1), h2u(H2), h2u(H3));
            }
            // ---- prefetch next chunk (overlaps mma) ----
            {
                int nc = c + 1, nt2 = t;
                if (nc == 4) { nc = 0; nt2 = t + NPAIR; }
                if (nt2 < NTILES) {
                    const float4* xt = reinterpret_cast<const float4*>(
                        x + (size_t)nt2 * (128 * NN));
#pragma unroll
                    for (int i = 0; i < 4; i++) {
                        int v = i * 256 + tid;
                        int row = v >> 3, kb = v & 7;
                        const float4* p = xt + row * 64 + nc * 16 + kb * 2;
                        pre[2 * i] = p[0];
                        pre[2 * i + 1] = p[1];
                    }
                }
            }
            __syncthreads();

            // ---- mma over this K-chunk: passes wh and wl ----
            const unsigned abase = sbase + A_BUF;
            const unsigned bhbase = sbase + B_BASE + c * B_CHUNK;
            const unsigned blbase = bhbase + BL_OFF;
#pragma unroll
            for (int ks = 0; ks < 4; ks++) {
                unsigned a0[4], a1[4];
                unsigned kba = ((unsigned)(ks * 32) + akb) ^ phase;
                ldsm_x4(a0[0], a0[1], a0[2], a0[3], abase + arow * 128 + kba);
                ldsm_x4(a1[0], a1[1], a1[2], a1[3], abase + (arow + 16) * 128 + kba);
                unsigned kbb = ((unsigned)(ks * 32) + bkb) ^ phase;
#pragma unroll
                for (int nb2 = 0; nb2 < 4; nb2++) {
                    unsigned b[4];
                    ldsm_x4(b[0], b[1], b[2], b[3],
                            bhbase + (brow + nb2 * 16) * 128 + kbb);
                    mma16816(acc[0][2 * nb2], a0, b);
                    mma16816(acc[0][2 * nb2 + 1], a0, b + 2);
                    mma16816(acc[1][2 * nb2], a1, b);
                    mma16816(acc[1][2 * nb2 + 1], a1, b + 2);
                }
#pragma unroll
                for (int nb2 = 0; nb2 < 4; nb2++) {
                    unsigned b[4];
                    ldsm_x4(b[0], b[1], b[2], b[3],
                            blbase + (brow + nb2 * 16) * 128 + kbb);
                    mma16816(acc[0][2 * nb2], a0, b);
                    mma16816(acc[0][2 * nb2 + 1], a0, b + 2);
                    mma16816(acc[1][2 * nb2], a1, b);
                    mma16816(acc[1][2 * nb2 + 1], a1, b + 2);
                }
            }
            __syncthreads();
        }

        // ---- epilogue: direct STG of accumulator fragments ----
        {
            int r0 = t * 128 + wm + (lane >> 2);
            int c0 = h0 + wn + 2 * (lane & 3);
#pragma unroll
            for (int mt = 0; mt < 2; mt++) {
#pragma unroll
                for (int nt = 0; nt < 8; nt++) {
                    float* p = out + (size_t)(r0 + mt * 16) * NN + c0 + nt * 8;
                    *reinterpret_cast<float2*>(p) =
                        make_float2(acc[mt][nt][0], acc[mt][nt][1]);
                    *reinterpret_cast<float2*>(p + 8 * NN) =
                        make_float2(acc[mt][nt][2], acc[mt][nt][3]);
                }
            }
        }
    }
}

// ========================= launcher =========================
extern "C" void kernel_launch(void* const* d_in, const int* in_sizes, int n_in,
                              void* d_out, int out_size) {
    const float* x = (const float*)d_in[0];
    const float* W = (const float*)d_in[1];
    float* out = (float*)d_out;

    cudaFuncSetAttribute(gemm_kernel, cudaFuncAttributeMaxDynamicSharedMemorySize, SMEM_TOTAL);

    ata_kernel<<<128, 256>>>(W, 0);   // g_M  = W^T W
    ata_kernel<<<128, 256>>>(W, 1);   // g_M2 = M^2
    ata_kernel<<<128, 256>>>(W, 2);   // g_M4 = M2^2
    pi_kernel<<<1, 256>>>(W);         // 5 iters on M4 == 20 power iters; g_scale = 1/sigma
    convert_kernel<<<128, 256>>>(W);  // g_WH/g_WL = fp16 hi/lo of W*scale, diag zeroed
    gemm_kernel<<<GRID, THREADS, SMEM_TOTAL>>>(x, out);
}

// round 13
// speedup vs baseline: 1.0538x; 1.0538x over previous
#include <cuda_runtime.h>
#include <cuda_fp16.h>

// ---------------- problem / tiling constants ----------------
#define NN      256
#define NTILES  2048          // 262144 / 128 M-rows per tile
#define GRID    152           // persistent, 1 CTA / SM on GB300
#define NPAIR   (GRID / 2)    // CTA pairs walking the same M-tiles
#define THREADS 256

// ---------------- smem layout (bytes) ----------------
// B resident: wh only, 4 chunks of [128 n-rows x 64 k] fp16, 128B rows, SW128
#define B_BASE   0
#define B_CHUNK  16384
#define SMEM_TOTAL (4 * B_CHUNK)   // 65536

// ---------------- device globals (scratch; no runtime alloc) ----------------
__device__ float g_scale;
__device__ __align__(16) float  g_M [NN * NN];
__device__ __align__(16) float  g_M2[NN * NN];
__device__ __align__(16) float  g_M4[NN * NN];
__device__ __align__(16) __half g_WH[NN * NN];

// ---------------- helpers ----------------
__device__ __forceinline__ unsigned smem_u32(const void* p) {
    unsigned a;
    asm("{ .reg .u64 t; cvta.to.shared.u64 t, %1; cvt.u32.u64 %0, t; }" : "=r"(a) : "l"(p));
    return a;
}
__device__ __forceinline__ void ldsm_x4(unsigned& r0, unsigned& r1, unsigned& r2, unsigned& r3,
                                        unsigned addr) {
    asm volatile("ldmatrix.sync.aligned.m8n8.x4.shared.b16 {%0,%1,%2,%3}, [%4];"
                 : "=r"(r0), "=r"(r1), "=r"(r2), "=r"(r3) : "r"(addr));
}
__device__ __forceinline__ void mma16816(float* d, const unsigned* a, const unsigned* b) {
    asm volatile("mma.sync.aligned.m16n8k16.row.col.f32.f16.f16.f32 "
                 "{%0,%1,%2,%3}, {%4,%5,%6,%7}, {%8,%9}, {%0,%1,%2,%3};"
                 : "+f"(d[0]), "+f"(d[1]), "+f"(d[2]), "+f"(d[3])
                 : "r"(a[0]), "r"(a[1]), "r"(a[2]), "r"(a[3]), "r"(b[0]), "r"(b[1]));
}
__device__ __forceinline__ unsigned h2u(__half2 h) { return *reinterpret_cast<unsigned*>(&h); }

// ========================= prep: C = A^T A (256x256) =========================
// grid 128, block 256; CTA b computes output rows 2b, 2b+1.
// For symmetric A this is A^2 (used for the squaring chain).
__global__ void ata_kernel(const float* __restrict__ W, int mode) {
    const float* A = (mode == 0) ? W : (mode == 1 ? g_M : g_M2);
    float* C = (mode == 0) ? g_M : (mode == 1 ? g_M2 : g_M4);
    __shared__ float2 cols[NN];
    int b = blockIdx.x, t = threadIdx.x;
    cols[t] = make_float2(A[t * NN + 2 * b], A[t * NN + 2 * b + 1]);
    __syncthreads();
    float a0 = 0.f, a1 = 0.f, a2 = 0.f, a3 = 0.f;
#pragma unroll 16
    for (int k = 0; k < NN; k += 2) {
        float va = A[k * NN + t];
        float vb = A[(k + 1) * NN + t];
        float2 c0 = cols[k], c1 = cols[k + 1];
        a0 += c0.x * va; a1 += c0.y * va;
        a2 += c1.x * vb; a3 += c1.y * vb;
    }
    C[(2 * b) * NN + t] = a0 + a2;
    C[(2 * b + 1) * NN + t] = a1 + a3;
}

// ===== prep: v = normalize((M4)^5 v0) (== 20 power iters), scale = 1/(||W v||+1e-12) =====
__global__ void __launch_bounds__(1024) pi_kernel(const float* __restrict__ W) {
    __shared__ float vv[NN];
    __shared__ float part[4][NN];
    __shared__ float red[8];
    __shared__ float bro;
    int t = threadIdx.x, r = t & 255, kq = t >> 8;
    int lane = t & 31, w = t >> 5;
    if (t < 256) vv[t] = 0.0625f;  // 1/sqrt(256)
    __syncthreads();
    const float4* mr = reinterpret_cast<const float4*>(g_M4 + r * NN + kq * 64);
    const float4* wr = reinterpret_cast<const float4*>(W + r * NN + kq * 64);
    for (int it = 0; it < 6; it++) {
        const float4* src = (it < 5) ? mr : wr;
        float s = 0.f, s2 = 0.f;
#pragma unroll
        for (int j = 0; j < 8; j++) {
            float4 m = src[2 * j], n = src[2 * j + 1];
            int vb = kq * 64 + j * 8;
            s  += m.x * vv[vb]     + m.y * vv[vb + 1] + m.z * vv[vb + 2] + m.w * vv[vb + 3];
            s2 += n.x * vv[vb + 4] + n.y * vv[vb + 5] + n.z * vv[vb + 6] + n.w * vv[vb + 7];
        }
        part[kq][r] = s + s2;
        __syncthreads();
        float sv = 0.f;
        if (t < 256) {
            sv = part[0][t] + part[1][t] + part[2][t] + part[3][t];
            float ss = sv * sv;
#pragma unroll
            for (int o = 16; o; o >>= 1) ss += __shfl_xor_sync(0xffffffffu, ss, o);
            if (lane == 0) red[w] = ss;
        }
        __syncthreads();
        if (t == 0) {
            float ss = red[0] + red[1] + red[2] + red[3] + red[4] + red[5] + red[6] + red[7];
            bro = 1.f / (sqrtf(ss) + 1e-12f);
        }
        __syncthreads();
        if (it < 5) {
            if (t < 256) vv[t] = sv * bro;
            __syncthreads();
        } else if (t == 0) {
            g_scale = bro;   // 1/(||W v|| + 1e-12)
        }
    }
}

// ================= prep: W_eff -> fp16, zero diag =================
__global__ void convert_kernel(const float* __restrict__ W) {
    float sc = g_scale;
    int idx = blockIdx.x * 256 + threadIdx.x;
    int i = idx >> 8, j = idx & 255;
    float w = (i == j) ? 0.f : W[idx] * sc;
    g_WH[idx] = __float2half_rn(w);
}

// ========================= main GEMM: out = x16 @ Wh^T =========================
__global__ void __launch_bounds__(THREADS, 1)
gemm_kernel(const float* __restrict__ x, float* __restrict__ out) {
    extern __shared__ char sm[];
    unsigned sbase = smem_u32(sm);
    const int tid = threadIdx.x, wid = tid >> 5, lane = tid & 31;
    const int h0 = (blockIdx.x & 1) * 128;     // this CTA's N-half
    const int pair = blockIdx.x >> 1;
    const int wm = (wid & 3) * 32;             // warp M offset in tile
    const int wn = (wid >> 2) * 64;            // warp N offset in half

    // ---- resident B: wh rows [h0, h0+128), chunked SW128 ----
    {
        const uint4* WH = reinterpret_cast<const uint4*>(g_WH);
        for (int v = tid; v < 4096; v += THREADS) {
            int n = v >> 5, kb8 = v & 31;      // 32 x 16B units per 512B row
            int chunk = kb8 >> 3, kb = kb8 & 7;
            unsigned off = chunk * B_CHUNK + n * 128 + ((kb * 16) ^ ((n & 7) << 4));
            *reinterpret_cast<uint4*>(sm + B_BASE + off) = WH[(h0 + n) * 32 + kb8];
        }
    }
    __syncthreads();

    const unsigned brow = wn + ((lane >> 4) & 1) * 8 + (lane & 7);
    const unsigned bkb = ((lane >> 3) & 1) * 16;   // bytes
    const unsigned phase = (lane & 7) << 4;
    const int gid = lane >> 2, tig = lane & 3;

    for (int t = pair; t < NTILES; t += NPAIR) {
        float acc[2][8][4];
#pragma unroll
        for (int mt = 0; mt < 2; mt++)
#pragma unroll
            for (int nt = 0; nt < 8; nt++)
#pragma unroll
                for (int q = 0; q < 4; q++) acc[mt][nt][q] = 0.f;

        const float* xp = x + ((size_t)t * 128 + wm + gid) * NN + 2 * tig;

        for (int c = 0; c < 4; c++) {
            const unsigned bhbase = sbase + B_BASE + c * B_CHUNK;
#pragma unroll
            for (int ks = 0; ks < 4; ks++) {
                int k0 = c * 64 + ks * 16;
                // A fragments straight from global (m16n8k16 row layout)
                float2 f00 = *reinterpret_cast<const float2*>(xp + k0);
                float2 f10 = *reinterpret_cast<const float2*>(xp + 8 * NN + k0);
                float2 f01 = *reinterpret_cast<const float2*>(xp + k0 + 8);
                float2 f11 = *reinterpret_cast<const float2*>(xp + 8 * NN + k0 + 8);
                float2 g00 = *reinterpret_cast<const float2*>(xp + 16 * NN + k0);
                float2 g10 = *reinterpret_cast<const float2*>(xp + 24 * NN + k0);
                float2 g01 = *reinterpret_cast<const float2*>(xp + 16 * NN + k0 + 8);
                float2 g11 = *reinterpret_cast<const float2*>(xp + 24 * NN + k0 + 8);
                unsigned a0[4], a1[4];
                a0[0] = h2u(__float22half2_rn(f00));
                a0[1] = h2u(__float22half2_rn(f10));
                a0[2] = h2u(__float22half2_rn(f01));
                a0[3] = h2u(__float22half2_rn(f11));
                a1[0] = h2u(__float22half2_rn(g00));
                a1[1] = h2u(__float22half2_rn(g10));
                a1[2] = h2u(__float22half2_rn(g01));
                a1[3] = h2u(__float22half2_rn(g11));

                unsigned kbb = ((unsigned)(ks * 32) + bkb) ^ phase;
#pragma unroll
                for (int nb2 = 0; nb2 < 4; nb2++) {
                    unsigned b[4];
                    ldsm_x4(b[0], b[1], b[2], b[3],
                            bhbase + (brow + nb2 * 16) * 128 + kbb);
                    mma16816(acc[0][2 * nb2],     a0, b);
                    mma16816(acc[0][2 * nb2 + 1], a0, b + 2);
                    mma16816(acc[1][2 * nb2],     a1, b);
                    mma16816(acc[1][2 * nb2 + 1], a1, b + 2);
                }
            }
        }

        // ---- epilogue: direct STG of accumulator fragments ----
        {
            int r0 = t * 128 + wm + gid;
            int c0 = h0 + wn + 2 * tig;
#pragma unroll
            for (int mt = 0; mt < 2; mt++) {
#pragma unroll
                for (int nt = 0; nt < 8; nt++) {
                    float* p = out + (size_t)(r0 + mt * 16) * NN + c0 + nt * 8;
                    *reinterpret_cast<float2*>(p) =
                        make_float2(acc[mt][nt][0], acc[mt][nt][1]);
                    *reinterpret_cast<float2*>(p + 8 * NN) =
                        make_float2(acc[mt][nt][2], acc[mt][nt][3]);
                }
            }
        }
    }
}

// ========================= launcher =========================
extern "C" void kernel_launch(void* const* d_in, const int* in_sizes, int n_in,
                              void* d_out, int out_size) {
    const float* x = (const float*)d_in[0];
    const float* W = (const float*)d_in[1];
    float* out = (float*)d_out;

    cudaFuncSetAttribute(gemm_kernel, cudaFuncAttributeMaxDynamicSharedMemorySize, SMEM_TOTAL);

    ata_kernel<<<128, 256>>>(W, 0);   // g_M  = W^T W
    ata_kernel<<<128, 256>>>(W, 1);   // g_M2 = M^2
    ata_kernel<<<128, 256>>>(W, 2);   // g_M4 = M2^2
    pi_kernel<<<1, 1024>>>(W);        // 5 iters on M4 == 20 power iters; g_scale = 1/sigma
    convert_kernel<<<256, 256>>>(W);  // g_WH = fp16(W*scale), diag zeroed
    gemm_kernel<<<GRID, THREADS, SMEM_TOTAL>>>(x, out);
}

// round 14
// speedup vs baseline: 1.6328x; 1.5495x over previous
#include <cuda_runtime.h>
#include <cuda_fp16.h>

// ---------------- problem / tiling constants ----------------
#define NN      256
#define NTILES  2048          // 262144 / 128 M-rows per tile
#define GRID    152           // persistent, 1 CTA / SM on GB300
#define NPAIR   (GRID / 2)    // CTA pairs walking the same M-tiles
#define THREADS 256

// ---------------- smem layout (bytes) ----------------
// A ring: 4 stages of [128 rows x 64 k] fp32, pitch 72 floats (288B) per row
#define A_STAGE  36864                      // 128 * 288
#define A_PITCH  288
#define B_BASE   (4 * A_STAGE)              // 147456
#define B_CHUNK  16384                      // [128 n-rows x 64 k] fp16, 128B rows, SW128
#define SMEM_TOTAL (B_BASE + 4 * B_CHUNK)   // 212992

// ---------------- device globals (scratch; no runtime alloc) ----------------
__device__ __align__(16) float  g_M [NN * NN];
__device__ __align__(16) float  g_M2[NN * NN];
__device__ __align__(16) float  g_M4[NN * NN];
__device__ __align__(16) float  g_M8[NN * NN];
__device__ __align__(16) float  g_u[NN];     // M4 v0
__device__ __align__(16) float  g_t[NN];     // M8 u
__device__ __align__(16) float  g_v[NN];     // M8 t  (unnormalized v20)
__device__ __align__(16) float  g_y[NN];     // W v
__device__ __align__(16) __half g_WH[NN * NN];

// ---------------- helpers ----------------
__device__ __forceinline__ unsigned smem_u32(const void* p) {
    unsigned a;
    asm("{ .reg .u64 t; cvta.to.shared.u64 t, %1; cvt.u32.u64 %0, t; }" : "=r"(a) : "l"(p));
    return a;
}
__device__ __forceinline__ void ldsm_x4(unsigned& r0, unsigned& r1, unsigned& r2, unsigned& r3,
                                        unsigned addr) {
    asm volatile("ldmatrix.sync.aligned.m8n8.x4.shared.b16 {%0,%1,%2,%3}, [%4];"
                 : "=r"(r0), "=r"(r1), "=r"(r2), "=r"(r3) : "r"(addr));
}
__device__ __forceinline__ void mma16816(float* d, const unsigned* a, const unsigned* b) {
    asm volatile("mma.sync.aligned.m16n8k16.row.col.f32.f16.f16.f32 "
                 "{%0,%1,%2,%3}, {%4,%5,%6,%7}, {%8,%9}, {%0,%1,%2,%3};"
                 : "+f"(d[0]), "+f"(d[1]), "+f"(d[2]), "+f"(d[3])
                 : "r"(a[0]), "r"(a[1]), "r"(a[2]), "r"(a[3]), "r"(b[0]), "r"(b[1]));
}
__device__ __forceinline__ unsigned h2u(__half2 h) { return *reinterpret_cast<unsigned*>(&h); }

__device__ __forceinline__ float blk_sum(float val) {
    __shared__ float red[8];
    int lane = threadIdx.x & 31, w = threadIdx.x >> 5;
#pragma unroll
    for (int o = 16; o; o >>= 1) val += __shfl_xor_sync(0xffffffffu, val, o);
    if (lane == 0) red[w] = val;
    __syncthreads();
    float r = red[0] + red[1] + red[2] + red[3] + red[4] + red[5] + red[6] + red[7];
    __syncthreads();
    return r;
}

// ========================= prep: C = A^T A (+ optional matvec tap) =========================
// grid 128, block 256; CTA b computes output rows 2b, 2b+1.
// mode 0: W->M ; 1: M->M2 ; 2: M2->M4 and u = M4 v0 ; 3: M4->M8 and t = M8 u
__global__ void ata_kernel(const float* __restrict__ W, int mode) {
    const float* A = (mode == 0) ? W : (mode == 1 ? g_M : (mode == 2 ? g_M2 : g_M4));
    float* C = (mode == 0) ? g_M : (mode == 1 ? g_M2 : (mode == 2 ? g_M4 : g_M8));
    __shared__ float2 cols[NN];
    int b = blockIdx.x, t = threadIdx.x;
    cols[t] = make_float2(A[t * NN + 2 * b], A[t * NN + 2 * b + 1]);
    __syncthreads();
    float a0 = 0.f, a1 = 0.f, a2 = 0.f, a3 = 0.f;
#pragma unroll 16
    for (int k = 0; k < NN; k += 2) {
        float va = A[k * NN + t];
        float vb = A[(k + 1) * NN + t];
        float2 c0 = cols[k], c1 = cols[k + 1];
        a0 += c0.x * va; a1 += c0.y * va;
        a2 += c1.x * vb; a3 += c1.y * vb;
    }
    float r0 = a0 + a2, r1 = a1 + a3;
    C[(2 * b) * NN + t] = r0;
    C[(2 * b + 1) * NN + t] = r1;
    if (mode == 2) {               // u = M4 v0, v0 = 0.0625 everywhere
        float s0 = blk_sum(r0), s1 = blk_sum(r1);
        if (t == 0) { g_u[2 * b] = 0.0625f * s0; g_u[2 * b + 1] = 0.0625f * s1; }
    } else if (mode == 3) {        // t = M8 u
        float uv = g_u[t];
        float s0 = blk_sum(r0 * uv), s1 = blk_sum(r1 * uv);
        if (t == 0) { g_t[2 * b] = s0; g_t[2 * b + 1] = s1; }
    }
}

// ============ prep: matvec r = A * x  (grid 128, 2 rows per CTA) ============
// mode 0: g_v = M8 * g_t ; mode 1: g_y = W * g_v
__global__ void matvec_kernel(const float* __restrict__ W, int mode) {
    const float* A = (mode == 0) ? g_M8 : W;
    const float* xv = (mode == 0) ? g_t : g_v;
    float* r = (mode == 0) ? g_v : g_y;
    int b = blockIdx.x, t = threadIdx.x;
    float xc = xv[t];
    float p0 = A[(2 * b) * NN + t] * xc;
    float p1 = A[(2 * b + 1) * NN + t] * xc;
    float s0 = blk_sum(p0), s1 = blk_sum(p1);
    if (t == 0) { r[2 * b] = s0; r[2 * b + 1] = s1; }
}

// ====== prep: scale = 1/sigma (computed redundantly per CTA), W -> fp16, zero diag ======
__global__ void convert_kernel(const float* __restrict__ W) {
    int t = threadIdx.x;
    float v = g_v[t], y = g_y[t];
    float ssv = blk_sum(v * v);
    float ssy = blk_sum(y * y);
    float nv = sqrtf(ssv);
    float sigma = sqrtf(ssy) / nv + 1e-12f;   // ||W vhat|| + 1e-12
    float sc = 1.f / sigma;
    int base = (blockIdx.x * 256 + t) * 4;
#pragma unroll
    for (int q = 0; q < 4; q++) {
        int idx = base + q;
        int i = idx >> 8, j = idx & 255;
        float w = (i == j) ? 0.f : W[idx] * sc;
        g_WH[idx] = __float2half_rn(w);
    }
}

// ========================= main GEMM: out = x16 @ Wh^T =========================
__global__ void __launch_bounds__(THREADS, 1)
gemm_kernel(const float* __restrict__ x, float* __restrict__ out) {
    extern __shared__ char sm[];
    unsigned sbase = smem_u32(sm);
    const int tid = threadIdx.x, wid = tid >> 5, lane = tid & 31;
    const int h0 = (blockIdx.x & 1) * 128;     // this CTA's N-half
    const int pair = blockIdx.x >> 1;
    const int wm = (wid & 3) * 32;             // warp M offset in tile
    const int wn = (wid >> 2) * 64;            // warp N offset in half

    // ---- resident B: wh rows [h0, h0+128), chunked SW128 ----
    {
        const uint4* WH = reinterpret_cast<const uint4*>(g_WH);
        for (int v = tid; v < 4096; v += THREADS) {
            int n = v >> 5, kb8 = v & 31;      // 32 x 16B units per 512B row
            int chunk = kb8 >> 3, kb = kb8 & 7;
            unsigned off = chunk * B_CHUNK + n * 128 + ((kb * 16) ^ ((n & 7) << 4));
            *reinterpret_cast<uint4*>(sm + B_BASE + off) = WH[(h0 + n) * 32 + kb8];
        }
    }
    __syncthreads();

    const unsigned brow = wn + ((lane >> 4) & 1) * 8 + (lane & 7);
    const unsigned bkb = ((lane >> 3) & 1) * 16;   // bytes
    const unsigned phase = (lane & 7) << 4;
    const int gid = lane >> 2, tig = lane & 3;

    // ---- cp.async chunk issue state ----
    int ti = pair, ci = 0;
    auto issue = [&](int stage) {
        if (ti < NTILES) {
            const float* xt = x + (size_t)ti * (128 * NN);
#pragma unroll
            for (int i = 0; i < 8; i++) {
                int v = i * 256 + tid;
                int row = v >> 4, f4 = v & 15;         // 16 float4 per 64-float row
                unsigned dst = sbase + stage * A_STAGE + row * A_PITCH + f4 * 16;
                const float* src = xt + row * NN + ci * 64 + f4 * 4;
                asm volatile("cp.async.cg.shared.global [%0], [%1], 16;"
                             :: "r"(dst), "l"(src) : "memory");
            }
        }
        asm volatile("cp.async.commit_group;" ::: "memory");
        if (++ci == 4) { ci = 0; ti += NPAIR; }
    };

    issue(0); issue(1); issue(2);
    int scomp = 0;

    for (int t = pair; t < NTILES; t += NPAIR) {
        float acc[2][8][4];
#pragma unroll
        for (int mt = 0; mt < 2; mt++)
#pragma unroll
            for (int nt = 0; nt < 8; nt++)
#pragma unroll
                for (int q = 0; q < 4; q++) acc[mt][nt][q] = 0.f;

        for (int c = 0; c < 4; c++) {
            asm volatile("cp.async.wait_group 2;" ::: "memory");
            __syncthreads();

            const char* ast = sm + scomp * A_STAGE;
            const unsigned bhbase = sbase + B_BASE + c * B_CHUNK;
#pragma unroll
            for (int ks = 0; ks < 4; ks++) {
                const char* ap = ast + (wm + gid) * A_PITCH + ks * 64 + tig * 8;
                float2 f00 = *reinterpret_cast<const float2*>(ap);
                float2 f01 = *reinterpret_cast<const float2*>(ap + 32);
                float2 f10 = *reinterpret_cast<const float2*>(ap + 8 * A_PITCH);
                float2 f11 = *reinterpret_cast<const float2*>(ap + 8 * A_PITCH + 32);
                float2 g00 = *reinterpret_cast<const float2*>(ap + 16 * A_PITCH);
                float2 g01 = *reinterpret_cast<const float2*>(ap + 16 * A_PITCH + 32);
                float2 g10 = *reinterpret_cast<const float2*>(ap + 24 * A_PITCH);
                float2 g11 = *reinterpret_cast<const float2*>(ap + 24 * A_PITCH + 32);
                unsigned a0[4], a1[4];
                a0[0] = h2u(__float22half2_rn(f00));
                a0[1] = h2u(__float22half2_rn(f10));
                a0[2] = h2u(__float22half2_rn(f01));
                a0[3] = h2u(__float22half2_rn(f11));
                a1[0] = h2u(__float22half2_rn(g00));
                a1[1] = h2u(__float22half2_rn(g10));
                a1[2] = h2u(__float22half2_rn(g01));
                a1[3] = h2u(__float22half2_rn(g11));

                unsigned kbb = ((unsigned)(ks * 32) + bkb) ^ phase;
#pragma unroll
                for (int nb2 = 0; nb2 < 4; nb2++) {
                    unsigned b[4];
                    ldsm_x4(b[0], b[1], b[2], b[3],
                            bhbase + (brow + nb2 * 16) * 128 + kbb);
                    mma16816(acc[0][2 * nb2],     a0, b);
                    mma16816(acc[0][2 * nb2 + 1], a0, b + 2);
                    mma16816(acc[1][2 * nb2],     a1, b);
                    mma16816(acc[1][2 * nb2 + 1], a1, b + 2);
                }
            }
            issue((scomp + 3) & 3);
            scomp = (scomp + 1) & 3;
        }

        // ---- epilogue: direct STG of accumulator fragments ----
        {
            int r0 = t * 128 + wm + gid;
            int c0 = h0 + wn + 2 * tig;
#pragma unroll
            for (int mt = 0; mt < 2; mt++) {
#pragma unroll
                for (int nt = 0; nt < 8; nt++) {
                    float* p = out + (size_t)(r0 + mt * 16) * NN + c0 + nt * 8;
                    *reinterpret_cast<float2*>(p) =
                        make_float2(acc[mt][nt][0], acc[mt][nt][1]);
                    *reinterpret_cast<float2*>(p + 8 * NN) =
                        make_float2(acc[mt][nt][2], acc[mt][nt][3]);
                }
            }
        }
    }
}

// ========================= launcher =========================
extern "C" void kernel_launch(void* const* d_in, const int* in_sizes, int n_in,
                              void* d_out, int out_size) {
    const float* x = (const float*)d_in[0];
    const float* W = (const float*)d_in[1];
    float* out = (float*)d_out;

    cudaFuncSetAttribute(gemm_kernel, cudaFuncAttributeMaxDynamicSharedMemorySize, SMEM_TOTAL);

    ata_kernel<<<128, 256>>>(W, 0);     // g_M  = W^T W
    ata_kernel<<<128, 256>>>(W, 1);     // g_M2 = M^2
    ata_kernel<<<128, 256>>>(W, 2);     // g_M4 = M2^2 ; g_u = M4 v0
    ata_kernel<<<128, 256>>>(W, 3);     // g_M8 = M4^2 ; g_t = M8 g_u
    matvec_kernel<<<128, 256>>>(W, 0);  // g_v = M8 g_t   (== M^20 v0, unnormalized)
    matvec_kernel<<<128, 256>>>(W, 1);  // g_y = W g_v
    convert_kernel<<<64, 256>>>(W);     // scale = ||v||/(||y|| + eps||v||); g_WH = fp16(W*scale), diag 0
    gemm_kernel<<<GRID, THREADS, SMEM_TOTAL>>>(x, out);
}

// round 17
// speedup vs baseline: 1.7094x; 1.0469x over previous
#include <cuda_runtime.h>
#include <cuda_fp16.h>

// ---------------- problem / tiling constants ----------------
#define NN      256
#define NTILES  2048          // 262144 / 128 M-rows per tile
#define GRID    152           // persistent, 1 CTA / SM on GB300
#define NPAIR   (GRID / 2)    // CTA pairs walking the same M-tiles
#define THREADS 256

// ---------------- smem layout (bytes) ----------------
// A ring: 4 stages of [128 rows x 64 k] fp32, pitch 72 floats (288B) per row
#define A_STAGE  36864                      // 128 * 288
#define A_PITCH  288
#define B_BASE   (4 * A_STAGE)              // 147456
#define B_CHUNK  16384                      // [128 n-rows x 64 k] fp16, 128B rows, SW128
#define SMEM_TOTAL (B_BASE + 4 * B_CHUNK)   // 212992

// ---------------- device globals (scratch; no runtime alloc) ----------------
__device__ __align__(16) float  g_M [NN * NN];
__device__ __align__(16) float  g_M2[NN * NN];
__device__ __align__(16) float  g_M4[NN * NN];
__device__ __align__(16) __half g_WH[NN * NN];

// ---------------- helpers ----------------
__device__ __forceinline__ unsigned smem_u32(const void* p) {
    unsigned a;
    asm("{ .reg .u64 t; cvta.to.shared.u64 t, %1; cvt.u32.u64 %0, t; }" : "=r"(a) : "l"(p));
    return a;
}
__device__ __forceinline__ void ldsm_x4(unsigned& r0, unsigned& r1, unsigned& r2, unsigned& r3,
                                        unsigned addr) {
    asm volatile("ldmatrix.sync.aligned.m8n8.x4.shared.b16 {%0,%1,%2,%3}, [%4];"
                 : "=r"(r0), "=r"(r1), "=r"(r2), "=r"(r3) : "r"(addr));
}
__device__ __forceinline__ void mma16816(float* d, const unsigned* a, const unsigned* b) {
    asm volatile("mma.sync.aligned.m16n8k16.row.col.f32.f16.f16.f32 "
                 "{%0,%1,%2,%3}, {%4,%5,%6,%7}, {%8,%9}, {%0,%1,%2,%3};"
                 : "+f"(d[0]), "+f"(d[1]), "+f"(d[2]), "+f"(d[3])
                 : "r"(a[0]), "r"(a[1]), "r"(a[2]), "r"(a[3]), "r"(b[0]), "r"(b[1]));
}
__device__ __forceinline__ unsigned h2u(__half2 h) { return *reinterpret_cast<unsigned*>(&h); }

// ========================= prep: C = A^T A (256x256), smem-tiled =========================
// grid 256 (16x16 tiles of 16x16), block 256, one output element per thread.
// mode 0: W->M ; 1: M->M2 ; 2: M2->M4   (modes 1,2: A symmetric so A^T A = A^2)
__global__ void __launch_bounds__(256) ata_kernel(const float* __restrict__ W, int mode) {
    const float* A = (mode == 0) ? W : (mode == 1 ? g_M : g_M2);
    float* C = (mode == 0) ? g_M : (mode == 1 ? g_M2 : g_M4);
    __shared__ float As[NN][16];
    __shared__ float Bs[NN][16];
    int b = blockIdx.x, bi = b >> 4, bj = b & 15;
    int t = threadIdx.x;
    // stage the two 256x16 column panels (coalesced float4, high MLP)
#pragma unroll
    for (int i = 0; i < 4; i++) {
        int u = i * 256 + t;              // 0..1023, bijective over (row, q)
        int row = u >> 2, q = u & 3;
        float4 va = *reinterpret_cast<const float4*>(A + row * NN + bi * 16 + q * 4);
        float4 vb = *reinterpret_cast<const float4*>(A + row * NN + bj * 16 + q * 4);
        *reinterpret_cast<float4*>(&As[row][q * 4]) = va;
        *reinterpret_cast<float4*>(&Bs[row][q * 4]) = vb;
    }
    __syncthreads();
    int r = t >> 4, c = t & 15;
    float a0 = 0.f, a1 = 0.f;
#pragma unroll 16
    for (int k = 0; k < NN; k += 2) {
        a0 += As[k][r] * Bs[k][c];
        a1 += As[k + 1][r] * Bs[k + 1][c];
    }
    C[(bi * 16 + r) * NN + bj * 16 + c] = a0 + a1;
}

// ===== prep+convert (1024 threads, R13-proven 4-way k-split topology):
//   v = normalize((M4)^5 v0)  (== 20 reference power iterations, same directions)
//   sigma = sqrt(v^T M v) + 1e-12   (= ||W vhat|| + 1e-12 since M = W^T W)
//   g_WH = fp16(W / sigma), diag zeroed.  Redundant per CTA; grid 16. =====
__global__ void __launch_bounds__(1024) convert_kernel(const float* __restrict__ W) {
    __shared__ float v[NN];
    __shared__ float part[4][NN];
    __shared__ float red[8];
    __shared__ float bro;
    int t = threadIdx.x, r = t & 255, kq = t >> 8;   // column r, k-quarter kq
    int lane = t & 31, w = t >> 5;
    if (t < 256) v[t] = 0.0625f;                     // v0 = 1/sqrt(256)
    __syncthreads();
    for (int it = 0; it < 6; it++) {
        const float* A = (it < 5) ? g_M4 : g_M;
        // thread covers k in [64*kq, 64*kq+64) for column r; 4 indep accum streams
        float s0 = 0.f, s1 = 0.f, s2 = 0.f, s3 = 0.f;
        int kb = kq * 64;
#pragma unroll
        for (int k = 0; k < 64; k += 4) {
            s0 += A[(kb + k) * NN + r] * v[kb + k];
            s1 += A[(kb + k + 1) * NN + r] * v[kb + k + 1];
            s2 += A[(kb + k + 2) * NN + r] * v[kb + k + 2];
            s3 += A[(kb + k + 3) * NN + r] * v[kb + k + 3];
        }
        part[kq][r] = (s0 + s1) + (s2 + s3);
        __syncthreads();
        float sv = 0.f;
        if (t < 256) {
            sv = part[0][t] + part[1][t] + part[2][t] + part[3][t];
            float q = (it < 5) ? sv * sv : v[t] * sv;   // ||Mv||^2  or  v^T M v
#pragma unroll
            for (int o = 16; o; o >>= 1) q += __shfl_xor_sync(0xffffffffu, q, o);
            if (lane == 0) red[w] = q;                  // w in 0..7 for t<256
        }
        __syncthreads();
        if (t == 0) {
            float ss = red[0] + red[1] + red[2] + red[3]
                     + red[4] + red[5] + red[6] + red[7];
            bro = 1.f / (sqrtf(ss) + 1e-12f);           // it<5: 1/||Mv|| ; it=5: 1/sigma
        }
        __syncthreads();
        if (it < 5) {
            if (t < 256) v[t] = sv * bro;
            __syncthreads();
        }
    }
    float sc = bro;                                     // 1/sigma
    int base = blockIdx.x * 4096;                       // grid 16 covers 65536
#pragma unroll
    for (int q = 0; q < 4; q++) {
        int idx = base + q * 1024 + t;
        int i = idx >> 8, j = idx & 255;
        float ww = (i == j) ? 0.f : W[idx] * sc;
        g_WH[idx] = __float2half_rn(ww);
    }
}

// ========================= main GEMM: out = x16 @ Wh^T =========================
__global__ void __launch_bounds__(THREADS, 1)
gemm_kernel(const float* __restrict__ x, float* __restrict__ out) {
    extern __shared__ char sm[];
    unsigned sbase = smem_u32(sm);
    const int tid = threadIdx.x, wid = tid >> 5, lane = tid & 31;
    const int h0 = (blockIdx.x & 1) * 128;     // this CTA's N-half
    const int pair = blockIdx.x >> 1;
    const int wm = (wid & 3) * 32;             // warp M offset in tile
    const int wn = (wid >> 2) * 64;            // warp N offset in half

    // ---- resident B: wh rows [h0, h0+128), chunked SW128 ----
    {
        const uint4* WH = reinterpret_cast<const uint4*>(g_WH);
        for (int v = tid; v < 4096; v += THREADS) {
            int n = v >> 5, kb8 = v & 31;      // 32 x 16B units per 512B row
            int chunk = kb8 >> 3, kb = kb8 & 7;
            unsigned off = chunk * B_CHUNK + n * 128 + ((kb * 16) ^ ((n & 7) << 4));
            *reinterpret_cast<uint4*>(sm + B_BASE + off) = WH[(h0 + n) * 32 + kb8];
        }
    }
    __syncthreads();

    const unsigned brow = wn + ((lane >> 4) & 1) * 8 + (lane & 7);
    const unsigned bkb = ((lane >> 3) & 1) * 16;   // bytes
    const unsigned phase = (lane & 7) << 4;
    const int gid = lane >> 2, tig = lane & 3;

    // ---- cp.async chunk issue state ----
    int ti = pair, ci = 0;
    auto issue = [&](int stage) {
        if (ti < NTILES) {
            const float* xt = x + (size_t)ti * (128 * NN);
#pragma unroll
            for (int i = 0; i < 8; i++) {
                int v = i * 256 + tid;
                int row = v >> 4, f4 = v & 15;         // 16 float4 per 64-float row
                unsigned dst = sbase + stage * A_STAGE + row * A_PITCH + f4 * 16;
                const float* src = xt + row * NN + ci * 64 + f4 * 4;
                asm volatile("cp.async.cg.shared.global [%0], [%1], 16;"
                             :: "r"(dst), "l"(src) : "memory");
            }
        }
        asm volatile("cp.async.commit_group;" ::: "memory");
        if (++ci == 4) { ci = 0; ti += NPAIR; }
    };

    issue(0); issue(1); issue(2);
    int scomp = 0;

    for (int t = pair; t < NTILES; t += NPAIR) {
        float acc[2][8][4];
#pragma unroll
        for (int mt = 0; mt < 2; mt++)
#pragma unroll
            for (int nt = 0; nt < 8; nt++)
#pragma unroll
                for (int q = 0; q < 4; q++) acc[mt][nt][q] = 0.f;

        for (int c = 0; c < 4; c++) {
            asm volatile("cp.async.wait_group 2;" ::: "memory");
            __syncthreads();

            const char* ast = sm + scomp * A_STAGE;
            const unsigned bhbase = sbase + B_BASE + c * B_CHUNK;
#pragma unroll
            for (int ks = 0; ks < 4; ks++) {
                const char* ap = ast + (wm + gid) * A_PITCH + ks * 64 + tig * 8;
                float2 f00 = *reinterpret_cast<const float2*>(ap);
                float2 f01 = *reinterpret_cast<const float2*>(ap + 32);
                float2 f10 = *reinterpret_cast<const float2*>(ap + 8 * A_PITCH);
                float2 f11 = *reinterpret_cast<const float2*>(ap + 8 * A_PITCH + 32);
                float2 g00 = *reinterpret_cast<const float2*>(ap + 16 * A_PITCH);
                float2 g01 = *reinterpret_cast<const float2*>(ap + 16 * A_PITCH + 32);
                float2 g10 = *reinterpret_cast<const float2*>(ap + 24 * A_PITCH);
                float2 g11 = *reinterpret_cast<const float2*>(ap + 24 * A_PITCH + 32);
                unsigned a0[4], a1[4];
                a0[0] = h2u(__float22half2_rn(f00));
                a0[1] = h2u(__float22half2_rn(f10));
                a0[2] = h2u(__float22half2_rn(f01));
                a0[3] = h2u(__float22half2_rn(f11));
                a1[0] = h2u(__float22half2_rn(g00));
                a1[1] = h2u(__float22half2_rn(g10));
                a1[2] = h2u(__float22half2_rn(g01));
                a1[3] = h2u(__float22half2_rn(g11));

                unsigned kbb = ((unsigned)(ks * 32) + bkb) ^ phase;
#pragma unroll
                for (int nb2 = 0; nb2 < 4; nb2++) {
                    unsigned b[4];
                    ldsm_x4(b[0], b[1], b[2], b[3],
                            bhbase + (brow + nb2 * 16) * 128 + kbb);
                    mma16816(acc[0][2 * nb2],     a0, b);
                    mma16816(acc[0][2 * nb2 + 1], a0, b + 2);
                    mma16816(acc[1][2 * nb2],     a1, b);
                    mma16816(acc[1][2 * nb2 + 1], a1, b + 2);
                }
            }
            issue((scomp + 3) & 3);
            scomp = (scomp + 1) & 3;
        }

        // ---- epilogue: direct STG of accumulator fragments ----
        {
            int r0 = t * 128 + wm + gid;
            int c0 = h0 + wn + 2 * tig;
#pragma unroll
            for (int mt = 0; mt < 2; mt++) {
#pragma unroll
                for (int nt = 0; nt < 8; nt++) {
                    float* p = out + (size_t)(r0 + mt * 16) * NN + c0 + nt * 8;
                    *reinterpret_cast<float2*>(p) =
                        make_float2(acc[mt][nt][0], acc[mt][nt][1]);
                    *reinterpret_cast<float2*>(p + 8 * NN) =
                        make_float2(acc[mt][nt][2], acc[mt][nt][3]);
                }
            }
        }
    }
}

// ========================= launcher =========================
extern "C" void kernel_launch(void* const* d_in, const int* in_sizes, int n_in,
                              void* d_out, int out_size) {
    const float* x = (const float*)d_in[0];
    const float* W = (const float*)d_in[1];
    float* out = (float*)d_out;

    cudaFuncSetAttribute(gemm_kernel, cudaFuncAttributeMaxDynamicSharedMemorySize, SMEM_TOTAL);

    ata_kernel<<<256, 256>>>(W, 0);     // g_M  = W^T W
    ata_kernel<<<256, 256>>>(W, 1);     // g_M2 = M^2
    ata_kernel<<<256, 256>>>(W, 2);     // g_M4 = M2^2
    convert_kernel<<<16, 1024>>>(W);    // v=(M4)^5 v0 norm'd; sigma=sqrt(v^T M v)+eps; W->fp16
    gemm_kernel<<<GRID, THREADS, SMEM_TOTAL>>>(x, out);
}